// round 8
// baseline (speedup 1.0000x reference)
#include <cuda_runtime.h>
#include <cuda_bf16.h>
#include <cstdint>
#include <cstddef>

#define B_ROWS 4096
#define D_DIM  1024
#define N2     8192
#define INV_T  2.0f
#define QSCALE 127.0f
#define DEQ    (INV_T / (QSCALE * QSCALE))   // applied to s32 dot before exp
#define NT     64                  // 128-wide tiles per dimension
#define TT     (NT*(NT+1)/2)       // 2080 upper-triangular tiles

// Scratch (device globals; no allocation allowed)
__device__ int8_t        g_reps8[(size_t)N2 * D_DIM];  // normalized reps, int8 (GEMM)
__device__ __nv_bfloat16 g_repsb[(size_t)N2 * D_DIM];  // normalized reps, bf16 (positives)
__device__ float         g_rowsum[N2];

// ---------------------------------------------------------------------------
// Kernel 1: L2-normalize rows; write int8 + bf16 reps; zero accumulators
// ---------------------------------------------------------------------------
__global__ void normalize_kernel(const float* __restrict__ emb_i,
                                 const float* __restrict__ emb_j,
                                 float* __restrict__ out)
{
    int row = blockIdx.x;                       // 0..8191
    const float* src = (row < B_ROWS) ? (emb_i + (size_t)row * D_DIM)
                                      : (emb_j + (size_t)(row - B_ROWS) * D_DIM);
    int t = threadIdx.x;                        // 256 threads, 4 floats each
    float4 v = ((const float4*)src)[t];
    float ss = v.x * v.x + v.y * v.y + v.z * v.z + v.w * v.w;

    #pragma unroll
    for (int o = 16; o; o >>= 1) ss += __shfl_xor_sync(0xFFFFFFFFu, ss, o);

    __shared__ float warp_ss[8];
    if ((t & 31) == 0) warp_ss[t >> 5] = ss;
    __syncthreads();
    if (t < 32) {
        float s = (t < 8) ? warp_ss[t] : 0.0f;
        #pragma unroll
        for (int o = 4; o; o >>= 1) s += __shfl_xor_sync(0xFFFFFFFFu, s, o);
        if (t == 0) warp_ss[0] = s;
    }
    __syncthreads();

    float rinv = 1.0f / fmaxf(sqrtf(warp_ss[0]), 1e-12f);
    float nx = v.x * rinv, ny = v.y * rinv, nz = v.z * rinv, nw = v.w * rinv;

    // bf16 copy (for accurate positive dots)
    __nv_bfloat162* dstb = (__nv_bfloat162*)(g_repsb + (size_t)row * D_DIM);
    dstb[t * 2 + 0] = __float22bfloat162_rn(make_float2(nx, ny));
    dstb[t * 2 + 1] = __float22bfloat162_rn(make_float2(nz, nw));

    // int8 copy (for the big GEMM)
    int qa = __float2int_rn(nx * QSCALE);
    int qb = __float2int_rn(ny * QSCALE);
    int qc = __float2int_rn(nz * QSCALE);
    int qd = __float2int_rn(nw * QSCALE);
    uint32_t packed = (uint32_t)(qa & 0xFF) | ((uint32_t)(qb & 0xFF) << 8)
                    | ((uint32_t)(qc & 0xFF) << 16) | ((uint32_t)(qd & 0xFF) << 24);
    ((uint32_t*)(g_reps8 + (size_t)row * D_DIM))[t] = packed;

    if (blockIdx.x < 32) g_rowsum[blockIdx.x * 256 + t] = 0.0f;
    if (blockIdx.x == 0 && t == 0) out[0] = 0.0f;
}

// ---------------------------------------------------------------------------
// Kernel 2: fused exp(2 * Z Z^T) row-sum, upper-triangular tiles, INT8 IMMA.
// Off-diagonal tiles feed BOTH rowsum[r] and rowsum[c].
// CTA tile 128x128, BK=64 int8 (64B rows), 2-stage cp.async, mma.m16n8k32.s8.
// ---------------------------------------------------------------------------
#define BK    64                  // int8 elems (=bytes) per k-stage
#define NKT   (D_DIM / BK)        // 16 k-stages
#define SSTR  80                  // padded smem row stride in BYTES (64 + 16)

__global__ __launch_bounds__(256, 2)
void simexp_kernel()
{
    __shared__ uint8_t sA[2][128 * SSTR];
    __shared__ uint8_t sB[2][128 * SSTR];

    // decode linear tile index -> (by, bx) with bx >= by
    int idx = blockIdx.x;
    int by = (int)((2.0f * NT + 1.0f
              - sqrtf((float)((2 * NT + 1) * (2 * NT + 1) - 8 * idx))) * 0.5f);
    while ((by * (2 * NT - by + 1)) / 2 > idx) by--;
    while (((by + 1) * (2 * NT - by)) / 2 <= idx) by++;
    int bx = by + idx - (by * (2 * NT - by + 1)) / 2;
    bool offdiag = (bx != by);

    int tid  = threadIdx.x;
    int wid  = tid >> 5, lane = tid & 31;
    int warp_m = wid & 1;     // 0..1  -> 64-row slab
    int warp_n = wid >> 1;    // 0..3  -> 32-col slab

    const int8_t* Abase = g_reps8 + (size_t)(by * 128) * D_DIM;
    const int8_t* Bbase = g_reps8 + (size_t)(bx * 128) * D_DIM;

    // cooperative cp.async: 128 rows x 64B per matrix = 512 16B-chunks, 2/thread
    int l_r  = tid >> 2;          // base row 0..63 (second item: +64)
    int l_c4 = tid & 3;           // 16B chunk within the 64B slab

    #define LOAD_STAGE(kt, st)                                                        \
    {                                                                                 \
        _Pragma("unroll")                                                             \
        for (int i = 0; i < 2; i++) {                                                 \
            int r = l_r + i * 64;                                                     \
            const int8_t* ga = Abase + (size_t)r * D_DIM + (kt) + l_c4 * 16;          \
            uint32_t da = (uint32_t)__cvta_generic_to_shared(                         \
                              &sA[st][r * SSTR + l_c4 * 16]);                         \
            asm volatile("cp.async.cg.shared.global [%0], [%1], 16;" ::               \
                         "r"(da), "l"(ga));                                           \
            const int8_t* gb = Bbase + (size_t)r * D_DIM + (kt) + l_c4 * 16;          \
            uint32_t db = (uint32_t)__cvta_generic_to_shared(                         \
                              &sB[st][r * SSTR + l_c4 * 16]);                         \
            asm volatile("cp.async.cg.shared.global [%0], [%1], 16;" ::               \
                         "r"(db), "l"(gb));                                           \
        }                                                                             \
        asm volatile("cp.async.commit_group;");                                       \
    }

    int acc[4][4][4];
    #pragma unroll
    for (int mi = 0; mi < 4; mi++)
        #pragma unroll
        for (int ni = 0; ni < 4; ni++)
            #pragma unroll
            for (int k = 0; k < 4; k++) acc[mi][ni][k] = 0;

    LOAD_STAGE(0, 0);

    for (int kt = 0; kt < NKT; kt++) {
        int st = kt & 1;
        if (kt + 1 < NKT) {
            LOAD_STAGE((kt + 1) * BK, (kt + 1) & 1);
            asm volatile("cp.async.wait_group 1;");
        } else {
            asm volatile("cp.async.wait_group 0;");
        }
        __syncthreads();

        #pragma unroll
        for (int ks = 0; ks < 2; ks++) {
            int kb = ks * 32;                            // byte offset of k32 chunk
            uint32_t a[4][4];
            #pragma unroll
            for (int mi = 0; mi < 4; mi++) {
                int row = warp_m * 64 + mi * 16 + (lane & 15);
                int col = kb + ((lane >> 4) << 4);       // 0 / 16 bytes
                uint32_t addr = (uint32_t)__cvta_generic_to_shared(&sA[st][row * SSTR + col]);
                asm volatile("ldmatrix.sync.aligned.m8n8.x4.shared.b16 {%0,%1,%2,%3}, [%4];"
                             : "=r"(a[mi][0]), "=r"(a[mi][1]), "=r"(a[mi][2]), "=r"(a[mi][3])
                             : "r"(addr));
            }
            uint32_t b[4][2];
            #pragma unroll
            for (int ni = 0; ni < 4; ni++) {
                int row = warp_n * 32 + ni * 8 + (lane & 7);
                int col = kb + (((lane >> 3) & 1) << 4); // 0 / 16 bytes
                uint32_t addr = (uint32_t)__cvta_generic_to_shared(&sB[st][row * SSTR + col]);
                asm volatile("ldmatrix.sync.aligned.m8n8.x2.shared.b16 {%0,%1}, [%2];"
                             : "=r"(b[ni][0]), "=r"(b[ni][1])
                             : "r"(addr));
            }
            #pragma unroll
            for (int mi = 0; mi < 4; mi++)
                #pragma unroll
                for (int ni = 0; ni < 4; ni++)
                    asm volatile(
                        "mma.sync.aligned.m16n8k32.row.col.s32.s8.s8.s32 "
                        "{%0,%1,%2,%3}, {%4,%5,%6,%7}, {%8,%9}, {%0,%1,%2,%3};"
                        : "+r"(acc[mi][ni][0]), "+r"(acc[mi][ni][1]),
                          "+r"(acc[mi][ni][2]), "+r"(acc[mi][ni][3])
                        : "r"(a[mi][0]), "r"(a[mi][1]), "r"(a[mi][2]), "r"(a[mi][3]),
                          "r"(b[ni][0]), "r"(b[ni][1]));
        }
        __syncthreads();
    }

    // ---------------- Epilogue ----------------
    int grow_base = by * 128 + warp_m * 64;
    int gcol_base = bx * 128 + warp_n * 32;
    int lr = lane >> 2;
    int lc = (lane & 3) * 2;

    float colacc[4][2];
    #pragma unroll
    for (int ni = 0; ni < 4; ni++) { colacc[ni][0] = 0.0f; colacc[ni][1] = 0.0f; }

    #pragma unroll
    for (int mi = 0; mi < 4; mi++) {
        int r0 = grow_base + mi * 16 + lr;
        int r1 = r0 + 8;
        float s0 = 0.0f, s1 = 0.0f;
        #pragma unroll
        for (int ni = 0; ni < 4; ni++) {
            int c0 = gcol_base + ni * 8 + lc;
            const int* v = acc[mi][ni];
            float e00 = (r0 != c0)     ? __expf((float)v[0] * DEQ) : 0.0f;
            float e01 = (r0 != c0 + 1) ? __expf((float)v[1] * DEQ) : 0.0f;
            float e10 = (r1 != c0)     ? __expf((float)v[2] * DEQ) : 0.0f;
            float e11 = (r1 != c0 + 1) ? __expf((float)v[3] * DEQ) : 0.0f;
            s0 += e00 + e01;
            s1 += e10 + e11;
            colacc[ni][0] += e00 + e10;
            colacc[ni][1] += e01 + e11;
        }
        s0 += __shfl_xor_sync(0xFFFFFFFFu, s0, 1);
        s0 += __shfl_xor_sync(0xFFFFFFFFu, s0, 2);
        s1 += __shfl_xor_sync(0xFFFFFFFFu, s1, 1);
        s1 += __shfl_xor_sync(0xFFFFFFFFu, s1, 2);
        if ((lane & 3) == 0) {
            atomicAdd(&g_rowsum[r0], s0);
            atomicAdd(&g_rowsum[r1], s1);
        }
    }

    if (offdiag) {
        #pragma unroll
        for (int ni = 0; ni < 4; ni++) {
            float c0 = colacc[ni][0], c1 = colacc[ni][1];
            #pragma unroll
            for (int o = 4; o <= 16; o <<= 1) {
                c0 += __shfl_xor_sync(0xFFFFFFFFu, c0, o);
                c1 += __shfl_xor_sync(0xFFFFFFFFu, c1, o);
            }
            if (lane < 4) {
                int c = gcol_base + ni * 8 + lane * 2;
                atomicAdd(&g_rowsum[c],     c0);
                atomicAdd(&g_rowsum[c + 1], c1);
            }
        }
    }
}

// ---------------------------------------------------------------------------
// Kernel 3: per-row positive dot (bf16) + log(denominator), scalar reduce
// ---------------------------------------------------------------------------
__global__ void finalize_kernel(float* __restrict__ out)
{
    int wid  = threadIdx.x >> 5;
    int lane = threadIdx.x & 31;
    int r = blockIdx.x * 8 + wid;
    int partner = (r < B_ROWS) ? (r + B_ROWS) : (r - B_ROWS);

    const __nv_bfloat16* zr = g_repsb + (size_t)r * D_DIM;
    const __nv_bfloat16* zp = g_repsb + (size_t)partner * D_DIM;

    float dot = 0.0f;
    #pragma unroll
    for (int i = 0; i < 4; i++) {
        int c = (lane * 4 + i) * 8;
        uint4 ua = *(const uint4*)(zr + c);
        uint4 ub = *(const uint4*)(zp + c);
        const __nv_bfloat162* pa = (const __nv_bfloat162*)&ua;
        const __nv_bfloat162* pb = (const __nv_bfloat162*)&ub;
        #pragma unroll
        for (int j = 0; j < 4; j++) {
            float2 fa = __bfloat1622float2(pa[j]);
            float2 fb = __bfloat1622float2(pb[j]);
            dot += fa.x * fb.x + fa.y * fb.y;
        }
    }
    #pragma unroll
    for (int o = 16; o; o >>= 1) dot += __shfl_xor_sync(0xFFFFFFFFu, dot, o);

    if (lane == 0) {
        float lp = logf(g_rowsum[r]) - dot * INV_T;
        atomicAdd(out, lp * (1.0f / (float)N2));
    }
}

// ---------------------------------------------------------------------------
extern "C" void kernel_launch(void* const* d_in, const int* in_sizes, int n_in,
                              void* d_out, int out_size)
{
    const float* emb_i = (const float*)d_in[0];
    const float* emb_j = (const float*)d_in[1];
    float* out = (float*)d_out;

    normalize_kernel<<<N2, 256>>>(emb_i, emb_j, out);
    simexp_kernel<<<TT, 256>>>();
    finalize_kernel<<<1024, 256>>>(out);
}

// round 9
// speedup vs baseline: 2.2833x; 2.2833x over previous
#include <cuda_runtime.h>
#include <cuda_bf16.h>
#include <cuda_fp16.h>
#include <cuda_fp8.h>
#include <cstdint>
#include <cstddef>

#define B_ROWS 4096
#define D_DIM  1024
#define N2     8192
#define INV_T  2.0f
#define NT     64                  // 128-wide tiles per dimension
#define TT     (NT*(NT+1)/2)       // 2080 upper-triangular tiles

// Scratch (device globals; no allocation allowed)
__device__ uint8_t       g_reps8[(size_t)N2 * D_DIM];  // normalized reps, e4m3 (GEMM)
__device__ __nv_bfloat16 g_repsb[(size_t)N2 * D_DIM];  // normalized reps, bf16 (positives)
__device__ float         g_rowsum[N2];

// ---------------------------------------------------------------------------
// Kernel 1: L2-normalize rows; write e4m3 + bf16 reps; zero accumulators
// ---------------------------------------------------------------------------
__global__ void normalize_kernel(const float* __restrict__ emb_i,
                                 const float* __restrict__ emb_j,
                                 float* __restrict__ out)
{
    int row = blockIdx.x;                       // 0..8191
    const float* src = (row < B_ROWS) ? (emb_i + (size_t)row * D_DIM)
                                      : (emb_j + (size_t)(row - B_ROWS) * D_DIM);
    int t = threadIdx.x;                        // 256 threads, 4 floats each
    float4 v = ((const float4*)src)[t];
    float ss = v.x * v.x + v.y * v.y + v.z * v.z + v.w * v.w;

    #pragma unroll
    for (int o = 16; o; o >>= 1) ss += __shfl_xor_sync(0xFFFFFFFFu, ss, o);

    __shared__ float warp_ss[8];
    if ((t & 31) == 0) warp_ss[t >> 5] = ss;
    __syncthreads();
    if (t < 32) {
        float s = (t < 8) ? warp_ss[t] : 0.0f;
        #pragma unroll
        for (int o = 4; o; o >>= 1) s += __shfl_xor_sync(0xFFFFFFFFu, s, o);
        if (t == 0) warp_ss[0] = s;
    }
    __syncthreads();

    float rinv = 1.0f / fmaxf(sqrtf(warp_ss[0]), 1e-12f);
    float nx = v.x * rinv, ny = v.y * rinv, nz = v.z * rinv, nw = v.w * rinv;

    // bf16 copy (for accurate positive dots)
    __nv_bfloat162* dstb = (__nv_bfloat162*)(g_repsb + (size_t)row * D_DIM);
    dstb[t * 2 + 0] = __float22bfloat162_rn(make_float2(nx, ny));
    dstb[t * 2 + 1] = __float22bfloat162_rn(make_float2(nz, nw));

    // e4m3 copy (for the big GEMM)
    __nv_fp8x2_e4m3 p0(make_float2(nx, ny));
    __nv_fp8x2_e4m3 p1(make_float2(nz, nw));
    uint32_t packed = (uint32_t)*(uint16_t*)&p0 | ((uint32_t)*(uint16_t*)&p1 << 16);
    ((uint32_t*)(g_reps8 + (size_t)row * D_DIM))[t] = packed;

    if (blockIdx.x < 32) g_rowsum[blockIdx.x * 256 + t] = 0.0f;
    if (blockIdx.x == 0 && t == 0) out[0] = 0.0f;
}

// ---------------------------------------------------------------------------
// Kernel 2: fused exp(2 * Z Z^T) row-sum, upper-triangular tiles.
// FP8 e4m3 QMMA with **f16 accumulators** (2x rate vs f32-accum on legacy pipe).
// CTA tile 128x128, BK=64 fp8 (64B rows), 2-stage cp.async, mma.m16n8k32.
// ---------------------------------------------------------------------------
#define BK    64                  // fp8 elems (=bytes) per k-stage
#define NKT   (D_DIM / BK)        // 16 k-stages
#define SSTR  80                  // padded smem row stride in BYTES (64 + 16)

__global__ __launch_bounds__(256, 2)
void simexp_kernel()
{
    __shared__ uint8_t sA[2][128 * SSTR];
    __shared__ uint8_t sB[2][128 * SSTR];

    // decode linear tile index -> (by, bx) with bx >= by
    int idx = blockIdx.x;
    int by = (int)((2.0f * NT + 1.0f
              - sqrtf((float)((2 * NT + 1) * (2 * NT + 1) - 8 * idx))) * 0.5f);
    while ((by * (2 * NT - by + 1)) / 2 > idx) by--;
    while (((by + 1) * (2 * NT - by)) / 2 <= idx) by++;
    int bx = by + idx - (by * (2 * NT - by + 1)) / 2;
    bool offdiag = (bx != by);

    int tid  = threadIdx.x;
    int wid  = tid >> 5, lane = tid & 31;
    int warp_m = wid & 1;     // 0..1  -> 64-row slab
    int warp_n = wid >> 1;    // 0..3  -> 32-col slab

    const uint8_t* Abase = g_reps8 + (size_t)(by * 128) * D_DIM;
    const uint8_t* Bbase = g_reps8 + (size_t)(bx * 128) * D_DIM;

    // cooperative cp.async: 128 rows x 64B per matrix = 512 16B-chunks, 2/thread
    int l_r  = tid >> 2;          // base row 0..63 (second item: +64)
    int l_c4 = tid & 3;           // 16B chunk within the 64B slab

    #define LOAD_STAGE(kt, st)                                                        \
    {                                                                                 \
        _Pragma("unroll")                                                             \
        for (int i = 0; i < 2; i++) {                                                 \
            int r = l_r + i * 64;                                                     \
            const uint8_t* ga = Abase + (size_t)r * D_DIM + (kt) + l_c4 * 16;         \
            uint32_t da = (uint32_t)__cvta_generic_to_shared(                         \
                              &sA[st][r * SSTR + l_c4 * 16]);                         \
            asm volatile("cp.async.cg.shared.global [%0], [%1], 16;" ::               \
                         "r"(da), "l"(ga));                                           \
            const uint8_t* gb = Bbase + (size_t)r * D_DIM + (kt) + l_c4 * 16;         \
            uint32_t db = (uint32_t)__cvta_generic_to_shared(                         \
                              &sB[st][r * SSTR + l_c4 * 16]);                         \
            asm volatile("cp.async.cg.shared.global [%0], [%1], 16;" ::               \
                         "r"(db), "l"(gb));                                           \
        }                                                                             \
        asm volatile("cp.async.commit_group;");                                       \
    }

    // f16x2 accumulators: [mi][ni][0] = row lr, cols (c,c+1); [1] = row lr+8
    uint32_t facc[4][4][2];
    #pragma unroll
    for (int mi = 0; mi < 4; mi++)
        #pragma unroll
        for (int ni = 0; ni < 4; ni++)
            { facc[mi][ni][0] = 0u; facc[mi][ni][1] = 0u; }

    LOAD_STAGE(0, 0);

    for (int kt = 0; kt < NKT; kt++) {
        int st = kt & 1;
        if (kt + 1 < NKT) {
            LOAD_STAGE((kt + 1) * BK, (kt + 1) & 1);
            asm volatile("cp.async.wait_group 1;");
        } else {
            asm volatile("cp.async.wait_group 0;");
        }
        __syncthreads();

        #pragma unroll
        for (int ks = 0; ks < 2; ks++) {
            int kb = ks * 32;                            // byte offset of k32 chunk
            uint32_t a[4][4];
            #pragma unroll
            for (int mi = 0; mi < 4; mi++) {
                int row = warp_m * 64 + mi * 16 + (lane & 15);
                int col = kb + ((lane >> 4) << 4);       // 0 / 16 bytes
                uint32_t addr = (uint32_t)__cvta_generic_to_shared(&sA[st][row * SSTR + col]);
                asm volatile("ldmatrix.sync.aligned.m8n8.x4.shared.b16 {%0,%1,%2,%3}, [%4];"
                             : "=r"(a[mi][0]), "=r"(a[mi][1]), "=r"(a[mi][2]), "=r"(a[mi][3])
                             : "r"(addr));
            }
            uint32_t b[4][2];
            #pragma unroll
            for (int ni = 0; ni < 4; ni++) {
                int row = warp_n * 32 + ni * 8 + (lane & 7);
                int col = kb + (((lane >> 3) & 1) << 4); // 0 / 16 bytes
                uint32_t addr = (uint32_t)__cvta_generic_to_shared(&sB[st][row * SSTR + col]);
                asm volatile("ldmatrix.sync.aligned.m8n8.x2.shared.b16 {%0,%1}, [%2];"
                             : "=r"(b[ni][0]), "=r"(b[ni][1])
                             : "r"(addr));
            }
            #pragma unroll
            for (int mi = 0; mi < 4; mi++)
                #pragma unroll
                for (int ni = 0; ni < 4; ni++)
                    asm volatile(
                        "mma.sync.aligned.m16n8k32.row.col.f16.e4m3.e4m3.f16 "
                        "{%0,%1}, {%2,%3,%4,%5}, {%6,%7}, {%0,%1};"
                        : "+r"(facc[mi][ni][0]), "+r"(facc[mi][ni][1])
                        : "r"(a[mi][0]), "r"(a[mi][1]), "r"(a[mi][2]), "r"(a[mi][3]),
                          "r"(b[ni][0]), "r"(b[ni][1]));
        }
        __syncthreads();
    }

    // ---------------- Epilogue ----------------
    int grow_base = by * 128 + warp_m * 64;
    int gcol_base = bx * 128 + warp_n * 32;
    int lr = lane >> 2;
    int lc = (lane & 3) * 2;

    float colacc[4][2];
    #pragma unroll
    for (int ni = 0; ni < 4; ni++) { colacc[ni][0] = 0.0f; colacc[ni][1] = 0.0f; }

    #pragma unroll
    for (int mi = 0; mi < 4; mi++) {
        int r0 = grow_base + mi * 16 + lr;
        int r1 = r0 + 8;
        float s0 = 0.0f, s1 = 0.0f;
        #pragma unroll
        for (int ni = 0; ni < 4; ni++) {
            int c0 = gcol_base + ni * 8 + lc;
            float2 v01 = __half22float2(*(const __half2*)&facc[mi][ni][0]);
            float2 v23 = __half22float2(*(const __half2*)&facc[mi][ni][1]);
            float e00 = (r0 != c0)     ? __expf(v01.x * INV_T) : 0.0f;
            float e01 = (r0 != c0 + 1) ? __expf(v01.y * INV_T) : 0.0f;
            float e10 = (r1 != c0)     ? __expf(v23.x * INV_T) : 0.0f;
            float e11 = (r1 != c0 + 1) ? __expf(v23.y * INV_T) : 0.0f;
            s0 += e00 + e01;
            s1 += e10 + e11;
            colacc[ni][0] += e00 + e10;
            colacc[ni][1] += e01 + e11;
        }
        s0 += __shfl_xor_sync(0xFFFFFFFFu, s0, 1);
        s0 += __shfl_xor_sync(0xFFFFFFFFu, s0, 2);
        s1 += __shfl_xor_sync(0xFFFFFFFFu, s1, 1);
        s1 += __shfl_xor_sync(0xFFFFFFFFu, s1, 2);
        if ((lane & 3) == 0) {
            atomicAdd(&g_rowsum[r0], s0);
            atomicAdd(&g_rowsum[r1], s1);
        }
    }

    if (offdiag) {
        #pragma unroll
        for (int ni = 0; ni < 4; ni++) {
            float c0 = colacc[ni][0], c1 = colacc[ni][1];
            #pragma unroll
            for (int o = 4; o <= 16; o <<= 1) {
                c0 += __shfl_xor_sync(0xFFFFFFFFu, c0, o);
                c1 += __shfl_xor_sync(0xFFFFFFFFu, c1, o);
            }
            if (lane < 4) {
                int c = gcol_base + ni * 8 + lane * 2;
                atomicAdd(&g_rowsum[c],     c0);
                atomicAdd(&g_rowsum[c + 1], c1);
            }
        }
    }
}

// ---------------------------------------------------------------------------
// Kernel 3: per-row positive dot (bf16) + log(denominator), scalar reduce
// ---------------------------------------------------------------------------
__global__ void finalize_kernel(float* __restrict__ out)
{
    int wid  = threadIdx.x >> 5;
    int lane = threadIdx.x & 31;
    int r = blockIdx.x * 8 + wid;
    int partner = (r < B_ROWS) ? (r + B_ROWS) : (r - B_ROWS);

    const __nv_bfloat16* zr = g_repsb + (size_t)r * D_DIM;
    const __nv_bfloat16* zp = g_repsb + (size_t)partner * D_DIM;

    float dot = 0.0f;
    #pragma unroll
    for (int i = 0; i < 4; i++) {
        int c = (lane * 4 + i) * 8;
        uint4 ua = *(const uint4*)(zr + c);
        uint4 ub = *(const uint4*)(zp + c);
        const __nv_bfloat162* pa = (const __nv_bfloat162*)&ua;
        const __nv_bfloat162* pb = (const __nv_bfloat162*)&ub;
        #pragma unroll
        for (int j = 0; j < 4; j++) {
            float2 fa = __bfloat1622float2(pa[j]);
            float2 fb = __bfloat1622float2(pb[j]);
            dot += fa.x * fb.x + fa.y * fb.y;
        }
    }
    #pragma unroll
    for (int o = 16; o; o >>= 1) dot += __shfl_xor_sync(0xFFFFFFFFu, dot, o);

    if (lane == 0) {
        float lp = logf(g_rowsum[r]) - dot * INV_T;
        atomicAdd(out, lp * (1.0f / (float)N2));
    }
}

// ---------------------------------------------------------------------------
extern "C" void kernel_launch(void* const* d_in, const int* in_sizes, int n_in,
                              void* d_out, int out_size)
{
    const float* emb_i = (const float*)d_in[0];
    const float* emb_j = (const float*)d_in[1];
    float* out = (float*)d_out;

    normalize_kernel<<<N2, 256>>>(emb_i, emb_j, out);
    simexp_kernel<<<TT, 256>>>();
    finalize_kernel<<<1024, 256>>>(out);
}

// round 10
// speedup vs baseline: 2.4246x; 1.0619x over previous
#include <cuda_runtime.h>
#include <cuda_bf16.h>
#include <cuda_fp16.h>
#include <cuda_fp8.h>
#include <cstdint>
#include <cstddef>

#define B_ROWS 4096
#define D_DIM  1024
#define N2     8192
#define INV_T  2.0f
#define NT     64                  // 128-wide tiles per dimension
#define TT     (NT*(NT+1)/2)       // 2080 upper-triangular tiles
#define PTILE_OFF 32               // bx == by + 32 tiles hold the positive pairs

// Scratch (device globals; no allocation allowed)
__device__ uint8_t g_reps8[(size_t)N2 * D_DIM];  // normalized reps, e4m3
__device__ float   g_rowsum[N2];                 // sum_{c != r} exp(sim[r][c]/T)
__device__ float   g_possum;                     // sum over r<B of sim(r, r+B)/T

// ---------------------------------------------------------------------------
// Kernel 1: L2-normalize rows -> e4m3 reps; zero accumulators
// ---------------------------------------------------------------------------
__global__ void normalize_kernel(const float* __restrict__ emb_i,
                                 const float* __restrict__ emb_j,
                                 float* __restrict__ out)
{
    int row = blockIdx.x;                       // 0..8191
    const float* src = (row < B_ROWS) ? (emb_i + (size_t)row * D_DIM)
                                      : (emb_j + (size_t)(row - B_ROWS) * D_DIM);
    int t = threadIdx.x;                        // 256 threads, 4 floats each
    float4 v = ((const float4*)src)[t];
    float ss = v.x * v.x + v.y * v.y + v.z * v.z + v.w * v.w;

    #pragma unroll
    for (int o = 16; o; o >>= 1) ss += __shfl_xor_sync(0xFFFFFFFFu, ss, o);

    __shared__ float warp_ss[8];
    if ((t & 31) == 0) warp_ss[t >> 5] = ss;
    __syncthreads();
    if (t < 32) {
        float s = (t < 8) ? warp_ss[t] : 0.0f;
        #pragma unroll
        for (int o = 4; o; o >>= 1) s += __shfl_xor_sync(0xFFFFFFFFu, s, o);
        if (t == 0) warp_ss[0] = s;
    }
    __syncthreads();

    float rinv = 1.0f / fmaxf(sqrtf(warp_ss[0]), 1e-12f);
    float nx = v.x * rinv, ny = v.y * rinv, nz = v.z * rinv, nw = v.w * rinv;

    __nv_fp8x2_e4m3 p0(make_float2(nx, ny));
    __nv_fp8x2_e4m3 p1(make_float2(nz, nw));
    uint32_t packed = (uint32_t)*(uint16_t*)&p0 | ((uint32_t)*(uint16_t*)&p1 << 16);
    ((uint32_t*)(g_reps8 + (size_t)row * D_DIM))[t] = packed;

    if (blockIdx.x < 32) g_rowsum[blockIdx.x * 256 + t] = 0.0f;
    if (blockIdx.x == 0 && t == 0) { out[0] = 0.0f; g_possum = 0.0f; }
}

// ---------------------------------------------------------------------------
// Kernel 2: fused exp(2 * Z Z^T) row-sum, upper-triangular tiles.
// FP8 e4m3 QMMA with f16 accumulators. CTA tile 128x128, BK=64, 2-stage cp.async.
// Tiles with bx == by+32 also extract the positive-pair dots (tile diagonal).
// ---------------------------------------------------------------------------
#define BK    64                  // fp8 elems (=bytes) per k-stage
#define NKT   (D_DIM / BK)        // 16 k-stages
#define SSTR  80                  // padded smem row stride in BYTES (64 + 16)

__global__ __launch_bounds__(256, 2)
void simexp_kernel()
{
    __shared__ uint8_t sA[2][128 * SSTR];
    __shared__ uint8_t sB[2][128 * SSTR];

    // decode linear tile index -> (by, bx) with bx >= by
    int idx = blockIdx.x;
    int by = (int)((2.0f * NT + 1.0f
              - sqrtf((float)((2 * NT + 1) * (2 * NT + 1) - 8 * idx))) * 0.5f);
    while ((by * (2 * NT - by + 1)) / 2 > idx) by--;
    while (((by + 1) * (2 * NT - by)) / 2 <= idx) by++;
    int bx = by + idx - (by * (2 * NT - by + 1)) / 2;
    bool offdiag = (bx != by);
    bool postile = (bx == by + PTILE_OFF);

    int tid  = threadIdx.x;
    int wid  = tid >> 5, lane = tid & 31;
    int warp_m = wid & 1;     // 0..1  -> 64-row slab
    int warp_n = wid >> 1;    // 0..3  -> 32-col slab

    const uint8_t* Abase = g_reps8 + (size_t)(by * 128) * D_DIM;
    const uint8_t* Bbase = g_reps8 + (size_t)(bx * 128) * D_DIM;

    // cooperative cp.async: 128 rows x 64B per matrix = 512 16B-chunks, 2/thread
    int l_r  = tid >> 2;          // base row 0..63 (second item: +64)
    int l_c4 = tid & 3;           // 16B chunk within the 64B slab

    #define LOAD_STAGE(kt, st)                                                        \
    {                                                                                 \
        _Pragma("unroll")                                                             \
        for (int i = 0; i < 2; i++) {                                                 \
            int r = l_r + i * 64;                                                     \
            const uint8_t* ga = Abase + (size_t)r * D_DIM + (kt) + l_c4 * 16;         \
            uint32_t da = (uint32_t)__cvta_generic_to_shared(                         \
                              &sA[st][r * SSTR + l_c4 * 16]);                         \
            asm volatile("cp.async.cg.shared.global [%0], [%1], 16;" ::               \
                         "r"(da), "l"(ga));                                           \
            const uint8_t* gb = Bbase + (size_t)r * D_DIM + (kt) + l_c4 * 16;         \
            uint32_t db = (uint32_t)__cvta_generic_to_shared(                         \
                              &sB[st][r * SSTR + l_c4 * 16]);                         \
            asm volatile("cp.async.cg.shared.global [%0], [%1], 16;" ::               \
                         "r"(db), "l"(gb));                                           \
        }                                                                             \
        asm volatile("cp.async.commit_group;");                                       \
    }

    // f16x2 accumulators: [mi][ni][0] = row lr, cols (c,c+1); [1] = row lr+8
    uint32_t facc[4][4][2];
    #pragma unroll
    for (int mi = 0; mi < 4; mi++)
        #pragma unroll
        for (int ni = 0; ni < 4; ni++)
            { facc[mi][ni][0] = 0u; facc[mi][ni][1] = 0u; }

    LOAD_STAGE(0, 0);

    for (int kt = 0; kt < NKT; kt++) {
        int st = kt & 1;
        if (kt + 1 < NKT) {
            LOAD_STAGE((kt + 1) * BK, (kt + 1) & 1);
            asm volatile("cp.async.wait_group 1;");
        } else {
            asm volatile("cp.async.wait_group 0;");
        }
        __syncthreads();

        #pragma unroll
        for (int ks = 0; ks < 2; ks++) {
            int kb = ks * 32;                            // byte offset of k32 chunk
            uint32_t a[4][4];
            #pragma unroll
            for (int mi = 0; mi < 4; mi++) {
                int row = warp_m * 64 + mi * 16 + (lane & 15);
                int col = kb + ((lane >> 4) << 4);       // 0 / 16 bytes
                uint32_t addr = (uint32_t)__cvta_generic_to_shared(&sA[st][row * SSTR + col]);
                asm volatile("ldmatrix.sync.aligned.m8n8.x4.shared.b16 {%0,%1,%2,%3}, [%4];"
                             : "=r"(a[mi][0]), "=r"(a[mi][1]), "=r"(a[mi][2]), "=r"(a[mi][3])
                             : "r"(addr));
            }
            uint32_t b[4][2];
            #pragma unroll
            for (int ni = 0; ni < 4; ni++) {
                int row = warp_n * 32 + ni * 8 + (lane & 7);
                int col = kb + (((lane >> 3) & 1) << 4); // 0 / 16 bytes
                uint32_t addr = (uint32_t)__cvta_generic_to_shared(&sB[st][row * SSTR + col]);
                asm volatile("ldmatrix.sync.aligned.m8n8.x2.shared.b16 {%0,%1}, [%2];"
                             : "=r"(b[ni][0]), "=r"(b[ni][1])
                             : "r"(addr));
            }
            #pragma unroll
            for (int mi = 0; mi < 4; mi++)
                #pragma unroll
                for (int ni = 0; ni < 4; ni++)
                    asm volatile(
                        "mma.sync.aligned.m16n8k32.row.col.f16.e4m3.e4m3.f16 "
                        "{%0,%1}, {%2,%3,%4,%5}, {%6,%7}, {%0,%1};"
                        : "+r"(facc[mi][ni][0]), "+r"(facc[mi][ni][1])
                        : "r"(a[mi][0]), "r"(a[mi][1]), "r"(a[mi][2]), "r"(a[mi][3]),
                          "r"(b[ni][0]), "r"(b[ni][1]));
        }
        __syncthreads();
    }

    // ---------------- Epilogue ----------------
    int grow_base = by * 128 + warp_m * 64;
    int gcol_base = bx * 128 + warp_n * 32;
    int lr = lane >> 2;
    int lc = (lane & 3) * 2;

    float colacc[4][2];
    #pragma unroll
    for (int ni = 0; ni < 4; ni++) { colacc[ni][0] = 0.0f; colacc[ni][1] = 0.0f; }

    #pragma unroll
    for (int mi = 0; mi < 4; mi++) {
        int r0 = grow_base + mi * 16 + lr;
        int r1 = r0 + 8;
        float s0 = 0.0f, s1 = 0.0f;
        #pragma unroll
        for (int ni = 0; ni < 4; ni++) {
            int c0 = gcol_base + ni * 8 + lc;
            float2 v01 = __half22float2(*(const __half2*)&facc[mi][ni][0]);
            float2 v23 = __half22float2(*(const __half2*)&facc[mi][ni][1]);
            float e00 = (r0 != c0)     ? __expf(v01.x * INV_T) : 0.0f;
            float e01 = (r0 != c0 + 1) ? __expf(v01.y * INV_T) : 0.0f;
            float e10 = (r1 != c0)     ? __expf(v23.x * INV_T) : 0.0f;
            float e11 = (r1 != c0 + 1) ? __expf(v23.y * INV_T) : 0.0f;
            s0 += e00 + e01;
            s1 += e10 + e11;
            colacc[ni][0] += e00 + e10;
            colacc[ni][1] += e01 + e11;
        }
        s0 += __shfl_xor_sync(0xFFFFFFFFu, s0, 1);
        s0 += __shfl_xor_sync(0xFFFFFFFFu, s0, 2);
        s1 += __shfl_xor_sync(0xFFFFFFFFu, s1, 1);
        s1 += __shfl_xor_sync(0xFFFFFFFFu, s1, 2);
        if ((lane & 3) == 0) {
            atomicAdd(&g_rowsum[r0], s0);
            atomicAdd(&g_rowsum[r1], s1);
        }
    }

    if (offdiag) {
        #pragma unroll
        for (int ni = 0; ni < 4; ni++) {
            float c0 = colacc[ni][0], c1 = colacc[ni][1];
            #pragma unroll
            for (int o = 4; o <= 16; o <<= 1) {
                c0 += __shfl_xor_sync(0xFFFFFFFFu, c0, o);
                c1 += __shfl_xor_sync(0xFFFFFFFFu, c1, o);
            }
            if (lane < 4) {
                int c = gcol_base + ni * 8 + lane * 2;
                atomicAdd(&g_rowsum[c],     c0);
                atomicAdd(&g_rowsum[c + 1], c1);
            }
        }
    }

    // positive-pair extraction: global (r, r + B_ROWS) lies on this tile's diagonal
    if (postile) {
        float pacc = 0.0f;
        #pragma unroll
        for (int mi = 0; mi < 4; mi++) {
            int r0 = grow_base + mi * 16 + lr;
            int r1 = r0 + 8;
            #pragma unroll
            for (int ni = 0; ni < 4; ni++) {
                int c0 = gcol_base + ni * 8 + lc;
                float2 v01 = __half22float2(*(const __half2*)&facc[mi][ni][0]);
                float2 v23 = __half22float2(*(const __half2*)&facc[mi][ni][1]);
                if (c0 == r0 + B_ROWS)     pacc += v01.x * INV_T;
                if (c0 + 1 == r0 + B_ROWS) pacc += v01.y * INV_T;
                if (c0 == r1 + B_ROWS)     pacc += v23.x * INV_T;
                if (c0 + 1 == r1 + B_ROWS) pacc += v23.y * INV_T;
            }
        }
        #pragma unroll
        for (int o = 16; o; o >>= 1) pacc += __shfl_xor_sync(0xFFFFFFFFu, pacc, o);
        if (lane == 0 && pacc != 0.0f) atomicAdd(&g_possum, pacc);
    }
}

// ---------------------------------------------------------------------------
// Kernel 3: loss = mean(log rowsum) - (2/N2) * possum
// ---------------------------------------------------------------------------
__global__ void finalize_kernel(float* __restrict__ out)
{
    int r = blockIdx.x * 1024 + threadIdx.x;     // 8 blocks x 1024
    float lp = logf(g_rowsum[r]);

    #pragma unroll
    for (int o = 16; o; o >>= 1) lp += __shfl_xor_sync(0xFFFFFFFFu, lp, o);

    __shared__ float wsum[32];
    int wid = threadIdx.x >> 5, lane = threadIdx.x & 31;
    if (lane == 0) wsum[wid] = lp;
    __syncthreads();
    if (wid == 0) {
        float s = wsum[lane];
        #pragma unroll
        for (int o = 16; o; o >>= 1) s += __shfl_xor_sync(0xFFFFFFFFu, s, o);
        if (lane == 0) {
            float contrib = s * (1.0f / (float)N2);
            if (blockIdx.x == 0) contrib -= g_possum * (2.0f / (float)N2);
            atomicAdd(out, contrib);
        }
    }
}

// ---------------------------------------------------------------------------
extern "C" void kernel_launch(void* const* d_in, const int* in_sizes, int n_in,
                              void* d_out, int out_size)
{
    const float* emb_i = (const float*)d_in[0];
    const float* emb_j = (const float*)d_in[1];
    float* out = (float*)d_out;

    normalize_kernel<<<N2, 256>>>(emb_i, emb_j, out);
    simexp_kernel<<<TT, 256>>>();
    finalize_kernel<<<8, 1024>>>(out);
}

// round 11
// speedup vs baseline: 2.4314x; 1.0028x over previous
#include <cuda_runtime.h>
#include <cuda_bf16.h>
#include <cuda_fp16.h>
#include <cuda_fp8.h>
#include <cstdint>
#include <cstddef>

#define B_ROWS 4096
#define D_DIM  1024
#define N2     8192
#define INV_T  2.0f
#define NT     64                  // 128-wide tiles per dimension
#define TT     (NT*(NT+1)/2)       // 2080 upper-triangular tiles
#define PTILE_OFF 32               // bx == by + 32 tiles hold the positive pairs

// Scratch (device globals; no allocation allowed)
__device__ uint8_t g_reps8[(size_t)N2 * D_DIM];  // normalized reps, e4m3
__device__ float   g_rowsum[N2];                 // sum_{c != r} exp(sim[r][c]/T)
__device__ float   g_possum;                     // sum over r<B of sim(r, r+B)/T
__device__ unsigned int g_done;                  // simexp completion counter

// ---------------------------------------------------------------------------
// Kernel 1: L2-normalize rows -> e4m3 reps; warp-per-row (MLP=8, no smem)
// ---------------------------------------------------------------------------
__global__ void normalize_kernel(const float* __restrict__ emb_i,
                                 const float* __restrict__ emb_j,
                                 float* __restrict__ out)
{
    int t = threadIdx.x;
    int wid = t >> 5, lane = t & 31;
    int row = blockIdx.x * 8 + wid;              // 1024 blocks x 8 warps
    const float* src = (row < B_ROWS) ? (emb_i + (size_t)row * D_DIM)
                                      : (emb_j + (size_t)(row - B_ROWS) * D_DIM);

    float4 v[8];
    #pragma unroll
    for (int i = 0; i < 8; i++) v[i] = ((const float4*)src)[i * 32 + lane];

    float ss = 0.0f;
    #pragma unroll
    for (int i = 0; i < 8; i++)
        ss += v[i].x * v[i].x + v[i].y * v[i].y + v[i].z * v[i].z + v[i].w * v[i].w;
    #pragma unroll
    for (int o = 16; o; o >>= 1) ss += __shfl_xor_sync(0xFFFFFFFFu, ss, o);

    float rinv = 1.0f / fmaxf(sqrtf(ss), 1e-12f);

    uint32_t* dst = (uint32_t*)(g_reps8 + (size_t)row * D_DIM);
    #pragma unroll
    for (int i = 0; i < 8; i++) {
        __nv_fp8x2_e4m3 p0(make_float2(v[i].x * rinv, v[i].y * rinv));
        __nv_fp8x2_e4m3 p1(make_float2(v[i].z * rinv, v[i].w * rinv));
        dst[i * 32 + lane] = (uint32_t)*(uint16_t*)&p0 | ((uint32_t)*(uint16_t*)&p1 << 16);
    }

    if (blockIdx.x < 32) g_rowsum[blockIdx.x * 256 + t] = 0.0f;
    if (blockIdx.x == 0 && t == 0) { out[0] = 0.0f; g_possum = 0.0f; g_done = 0u; }
}

// ---------------------------------------------------------------------------
// Kernel 2: fused exp(2 * Z Z^T) row-sum, upper-triangular tiles.
// FP8 e4m3 QMMA, f16 accumulators, 128x128 CTA tile, BK=64, 2-stage cp.async.
// Diagonal tiles skip the redundant lower-left quadrant (symmetry).
// Last CTA computes the final loss (fused finalize).
// ---------------------------------------------------------------------------
#define BK    64
#define NKT   (D_DIM / BK)        // 16 k-stages
#define SSTR  80                  // padded smem row stride in BYTES (64 + 16)

__global__ __launch_bounds__(256, 2)
void simexp_kernel(float* __restrict__ out)
{
    __shared__ uint8_t sA[2][128 * SSTR];
    __shared__ uint8_t sB[2][128 * SSTR];

    // decode linear tile index -> (by, bx) with bx >= by
    int idx = blockIdx.x;
    int by = (int)((2.0f * NT + 1.0f
              - sqrtf((float)((2 * NT + 1) * (2 * NT + 1) - 8 * idx))) * 0.5f);
    while ((by * (2 * NT - by + 1)) / 2 > idx) by--;
    while (((by + 1) * (2 * NT - by)) / 2 <= idx) by++;
    int bx = by + idx - (by * (2 * NT - by + 1)) / 2;
    bool offdiag = (bx != by);
    bool postile = (bx == by + PTILE_OFF);

    int tid  = threadIdx.x;
    int wid  = tid >> 5, lane = tid & 31;
    int warp_m = wid & 1;     // 0..1  -> 64-row slab
    int warp_n = wid >> 1;    // 0..3  -> 32-col slab

    // diagonal-tile symmetry: lower-left quadrant (rows 64-127, cols 0-63) is
    // the mirror of upper-right (rows 0-63, cols 64-127) -> skip; recover its
    // rowsum contribution via column sums on the mirror quadrant.
    bool skip_warp = !offdiag && (warp_m == 1) && (warp_n < 2);
    bool do_col    = offdiag || ((warp_m == 0) && (warp_n >= 2));

    const uint8_t* Abase = g_reps8 + (size_t)(by * 128) * D_DIM;
    const uint8_t* Bbase = g_reps8 + (size_t)(bx * 128) * D_DIM;

    int l_r  = tid >> 2;
    int l_c4 = tid & 3;

    #define LOAD_STAGE(kt, st)                                                        \
    {                                                                                 \
        _Pragma("unroll")                                                             \
        for (int i = 0; i < 2; i++) {                                                 \
            int r = l_r + i * 64;                                                     \
            const uint8_t* ga = Abase + (size_t)r * D_DIM + (kt) + l_c4 * 16;         \
            uint32_t da = (uint32_t)__cvta_generic_to_shared(                         \
                              &sA[st][r * SSTR + l_c4 * 16]);                         \
            asm volatile("cp.async.cg.shared.global [%0], [%1], 16;" ::               \
                         "r"(da), "l"(ga));                                           \
            const uint8_t* gb = Bbase + (size_t)r * D_DIM + (kt) + l_c4 * 16;         \
            uint32_t db = (uint32_t)__cvta_generic_to_shared(                         \
                              &sB[st][r * SSTR + l_c4 * 16]);                         \
            asm volatile("cp.async.cg.shared.global [%0], [%1], 16;" ::               \
                         "r"(db), "l"(gb));                                           \
        }                                                                             \
        asm volatile("cp.async.commit_group;");                                       \
    }

    uint32_t facc[4][4][2];
    #pragma unroll
    for (int mi = 0; mi < 4; mi++)
        #pragma unroll
        for (int ni = 0; ni < 4; ni++)
            { facc[mi][ni][0] = 0u; facc[mi][ni][1] = 0u; }

    LOAD_STAGE(0, 0);

    for (int kt = 0; kt < NKT; kt++) {
        int st = kt & 1;
        if (kt + 1 < NKT) {
            LOAD_STAGE((kt + 1) * BK, (kt + 1) & 1);
            asm volatile("cp.async.wait_group 1;");
        } else {
            asm volatile("cp.async.wait_group 0;");
        }
        __syncthreads();

        if (!skip_warp) {
            #pragma unroll
            for (int ks = 0; ks < 2; ks++) {
                int kb = ks * 32;
                uint32_t a[4][4];
                #pragma unroll
                for (int mi = 0; mi < 4; mi++) {
                    int row = warp_m * 64 + mi * 16 + (lane & 15);
                    int col = kb + ((lane >> 4) << 4);
                    uint32_t addr = (uint32_t)__cvta_generic_to_shared(&sA[st][row * SSTR + col]);
                    asm volatile("ldmatrix.sync.aligned.m8n8.x4.shared.b16 {%0,%1,%2,%3}, [%4];"
                                 : "=r"(a[mi][0]), "=r"(a[mi][1]), "=r"(a[mi][2]), "=r"(a[mi][3])
                                 : "r"(addr));
                }
                uint32_t b[4][2];
                #pragma unroll
                for (int ni = 0; ni < 4; ni++) {
                    int row = warp_n * 32 + ni * 8 + (lane & 7);
                    int col = kb + (((lane >> 3) & 1) << 4);
                    uint32_t addr = (uint32_t)__cvta_generic_to_shared(&sB[st][row * SSTR + col]);
                    asm volatile("ldmatrix.sync.aligned.m8n8.x2.shared.b16 {%0,%1}, [%2];"
                                 : "=r"(b[ni][0]), "=r"(b[ni][1])
                                 : "r"(addr));
                }
                #pragma unroll
                for (int mi = 0; mi < 4; mi++)
                    #pragma unroll
                    for (int ni = 0; ni < 4; ni++)
                        asm volatile(
                            "mma.sync.aligned.m16n8k32.row.col.f16.e4m3.e4m3.f16 "
                            "{%0,%1}, {%2,%3,%4,%5}, {%6,%7}, {%0,%1};"
                            : "+r"(facc[mi][ni][0]), "+r"(facc[mi][ni][1])
                            : "r"(a[mi][0]), "r"(a[mi][1]), "r"(a[mi][2]), "r"(a[mi][3]),
                              "r"(b[ni][0]), "r"(b[ni][1]));
            }
        }
        __syncthreads();
    }

    // ---------------- Epilogue ----------------
    int grow_base = by * 128 + warp_m * 64;
    int gcol_base = bx * 128 + warp_n * 32;
    int lr = lane >> 2;
    int lc = (lane & 3) * 2;

    if (!skip_warp) {
        float colacc[4][2];
        #pragma unroll
        for (int ni = 0; ni < 4; ni++) { colacc[ni][0] = 0.0f; colacc[ni][1] = 0.0f; }

        #pragma unroll
        for (int mi = 0; mi < 4; mi++) {
            int r0 = grow_base + mi * 16 + lr;
            int r1 = r0 + 8;
            float s0 = 0.0f, s1 = 0.0f;
            #pragma unroll
            for (int ni = 0; ni < 4; ni++) {
                int c0 = gcol_base + ni * 8 + lc;
                float2 v01 = __half22float2(*(const __half2*)&facc[mi][ni][0]);
                float2 v23 = __half22float2(*(const __half2*)&facc[mi][ni][1]);
                float e00 = (r0 != c0)     ? __expf(v01.x * INV_T) : 0.0f;
                float e01 = (r0 != c0 + 1) ? __expf(v01.y * INV_T) : 0.0f;
                float e10 = (r1 != c0)     ? __expf(v23.x * INV_T) : 0.0f;
                float e11 = (r1 != c0 + 1) ? __expf(v23.y * INV_T) : 0.0f;
                s0 += e00 + e01;
                s1 += e10 + e11;
                colacc[ni][0] += e00 + e10;
                colacc[ni][1] += e01 + e11;
            }
            s0 += __shfl_xor_sync(0xFFFFFFFFu, s0, 1);
            s0 += __shfl_xor_sync(0xFFFFFFFFu, s0, 2);
            s1 += __shfl_xor_sync(0xFFFFFFFFu, s1, 1);
            s1 += __shfl_xor_sync(0xFFFFFFFFu, s1, 2);
            if ((lane & 3) == 0) {
                atomicAdd(&g_rowsum[r0], s0);
                atomicAdd(&g_rowsum[r1], s1);
            }
        }

        if (do_col) {
            #pragma unroll
            for (int ni = 0; ni < 4; ni++) {
                float c0 = colacc[ni][0], c1 = colacc[ni][1];
                #pragma unroll
                for (int o = 4; o <= 16; o <<= 1) {
                    c0 += __shfl_xor_sync(0xFFFFFFFFu, c0, o);
                    c1 += __shfl_xor_sync(0xFFFFFFFFu, c1, o);
                }
                if (lane < 4) {
                    int c = gcol_base + ni * 8 + lane * 2;
                    atomicAdd(&g_rowsum[c],     c0);
                    atomicAdd(&g_rowsum[c + 1], c1);
                }
            }
        }

        // positive-pair extraction on bx == by + 32 tiles (tile diagonal)
        if (postile) {
            float pacc = 0.0f;
            #pragma unroll
            for (int mi = 0; mi < 4; mi++) {
                int r0 = grow_base + mi * 16 + lr;
                int r1 = r0 + 8;
                #pragma unroll
                for (int ni = 0; ni < 4; ni++) {
                    int c0 = gcol_base + ni * 8 + lc;
                    float2 v01 = __half22float2(*(const __half2*)&facc[mi][ni][0]);
                    float2 v23 = __half22float2(*(const __half2*)&facc[mi][ni][1]);
                    if (c0 == r0 + B_ROWS)     pacc += v01.x * INV_T;
                    if (c0 + 1 == r0 + B_ROWS) pacc += v01.y * INV_T;
                    if (c0 == r1 + B_ROWS)     pacc += v23.x * INV_T;
                    if (c0 + 1 == r1 + B_ROWS) pacc += v23.y * INV_T;
                }
            }
            #pragma unroll
            for (int o = 16; o; o >>= 1) pacc += __shfl_xor_sync(0xFFFFFFFFu, pacc, o);
            if (lane == 0 && pacc != 0.0f) atomicAdd(&g_possum, pacc);
        }
    }

    // ---------------- Fused finalize: last CTA computes the loss ----------
    __syncthreads();
    __threadfence();
    __shared__ unsigned int s_last;
    __shared__ float s_red[8];
    if (tid == 0) s_last = (atomicAdd(&g_done, 1u) == TT - 1) ? 1u : 0u;
    __syncthreads();
    if (s_last) {
        __threadfence();                           // acquire all CTAs' atomics
        float lsum = 0.0f;
        for (int r = tid; r < N2; r += 256) lsum += logf(g_rowsum[r]);
        #pragma unroll
        for (int o = 16; o; o >>= 1) lsum += __shfl_xor_sync(0xFFFFFFFFu, lsum, o);
        if (lane == 0) s_red[wid] = lsum;
        __syncthreads();
        if (tid < 32) {
            float s = (tid < 8) ? s_red[tid] : 0.0f;
            #pragma unroll
            for (int o = 4; o; o >>= 1) s += __shfl_xor_sync(0xFFFFFFFFu, s, o);
            if (tid == 0)
                out[0] = (s - 2.0f * g_possum) * (1.0f / (float)N2);
        }
    }
}

// ---------------------------------------------------------------------------
extern "C" void kernel_launch(void* const* d_in, const int* in_sizes, int n_in,
                              void* d_out, int out_size)
{
    const float* emb_i = (const float*)d_in[0];
    const float* emb_j = (const float*)d_in[1];
    float* out = (float*)d_out;

    normalize_kernel<<<1024, 256>>>(emb_i, emb_j, out);
    simexp_kernel<<<TT, 256>>>(out);
}